// round 7
// baseline (speedup 1.0000x reference)
#include <cuda_runtime.h>
#include <math.h>

#define N_MAX 100000
#define E_MAX 1600000
#define G_NUM 1024
#define SCAN_B 1024
#define NBLK_MAX 128   // ceil(100000/1024)=98

// ---------------- device scratch (no allocation allowed) -------------------
__device__ __align__(16) float g_H [(long long)N_MAX * 64]; // transformed feats
__device__ __align__(16) float g_A0[(long long)N_MAX * 64]; // agg ping
__device__ __align__(16) float g_A1[(long long)N_MAX * 64]; // agg pong
__device__ float g_dinv[N_MAX];
__device__ int   g_deg [N_MAX];
__device__ int   g_tmp [N_MAX];        // block-scan partials
__device__ int   g_off [N_MAX + 1];    // CSR offsets (by dst)
__device__ int   g_cur [N_MAX];        // fill cursors
__device__ int   g_bsum[NBLK_MAX];     // block sums for scan
__device__ int   g_csrc[E_MAX];        // CSR src ids
__device__ float g_cw  [E_MAX];        // CSR edge weights (norm)
__device__ float g_pool[G_NUM * 64];
__device__ float g_zbuf[G_NUM * 256];

__device__ __forceinline__ float* bufA(int s) { return s == 0 ? g_A0 : g_A1; }

// ---------------------------- prep -----------------------------------------
__global__ void k_zero(int n) {
    int i = blockIdx.x * blockDim.x + threadIdx.x;
    if (i < n)          g_deg[i]  = 0;
    if (i < G_NUM * 64) g_pool[i] = 0.f;
}

__global__ void k_degcount(const int* __restrict__ ei, int E) {
    int e = blockIdx.x * blockDim.x + threadIdx.x;
    if (e < E) atomicAdd(&g_deg[ei[E + e]], 1);
}

__global__ void k_dinv(int n) {
    int i = blockIdx.x * blockDim.x + threadIdx.x;
    if (i < n) g_dinv[i] = rsqrtf((float)(g_deg[i] + 1));  // +1 self loop
}

// ------------------------- 3-kernel exclusive scan --------------------------
__global__ void k_scan1(int n) {
    __shared__ int s[SCAN_B];
    int t = threadIdx.x;
    int i = blockIdx.x * SCAN_B + t;
    int v = (i < n) ? g_deg[i] : 0;
    s[t] = v;
    __syncthreads();
#pragma unroll
    for (int d = 1; d < SCAN_B; d <<= 1) {
        int x = (t >= d) ? s[t - d] : 0;
        __syncthreads();
        s[t] += x;
        __syncthreads();
    }
    if (i < n) g_tmp[i] = s[t];                 // inclusive
    if (t == SCAN_B - 1) g_bsum[blockIdx.x] = s[t];
}

__global__ void k_scan2(int nblk) {
    __shared__ int s[NBLK_MAX];
    int t = threadIdx.x;
    int v = (t < nblk) ? g_bsum[t] : 0;
    s[t] = v;
    __syncthreads();
#pragma unroll
    for (int d = 1; d < NBLK_MAX; d <<= 1) {
        int x = (t >= d) ? s[t - d] : 0;
        __syncthreads();
        s[t] += x;
        __syncthreads();
    }
    if (t < nblk) g_bsum[t] = s[t] - v;         // exclusive
}

__global__ void k_scan3(int n, int E) {
    int i = blockIdx.x * blockDim.x + threadIdx.x;
    if (i < n) {
        g_off[i] = g_tmp[i] - g_deg[i] + g_bsum[i / SCAN_B];  // exclusive
        g_cur[i] = 0;
    }
    if (i == 0) g_off[n] = E;
}

__global__ void k_fill(const int* __restrict__ ei, int E) {
    int e = blockIdx.x * blockDim.x + threadIdx.x;
    if (e >= E) return;
    int s = ei[e];
    int d = ei[E + e];
    int pos = g_off[d] + atomicAdd(&g_cur[d], 1);
    g_csrc[pos] = s;
    g_cw[pos]   = g_dinv[s] * g_dinv[d];
}

// ----------------- node transform: h = act(in) @ W ; agg = h*dinv^2 --------
template <int F_IN, int F_OUT, bool RELU_IN>
__global__ void k_transform(const float* __restrict__ x_ext,
                            int in_sel, int out_sel,
                            const float* __restrict__ W,
                            const float* __restrict__ bin, int n)
{
    __shared__ float sW[F_IN * F_OUT];
    __shared__ float sB[F_IN];
    for (int i = threadIdx.x; i < F_IN * F_OUT; i += blockDim.x) sW[i] = W[i];
    if (RELU_IN)
        for (int i = threadIdx.x; i < F_IN; i += blockDim.x) sB[i] = bin[i];
    __syncthreads();

    int node = blockIdx.x * blockDim.x + threadIdx.x;
    if (node >= n) return;

    const float* in = x_ext ? x_ext : bufA(in_sel);
    const float4* row4 = reinterpret_cast<const float4*>(in) +
                         (long long)node * (F_IN / 4);

    float acc[F_OUT];
#pragma unroll
    for (int j = 0; j < F_OUT; j++) acc[j] = 0.f;

    for (int k4 = 0; k4 < F_IN / 4; k4++) {
        float4 v4 = row4[k4];
        float vv[4] = {v4.x, v4.y, v4.z, v4.w};
#pragma unroll
        for (int u = 0; u < 4; u++) {
            int k = k4 * 4 + u;
            float v = vv[u];
            if (RELU_IN) v = fmaxf(v + sB[k], 0.f);
#pragma unroll
            for (int j = 0; j < F_OUT; j++)
                acc[j] = fmaf(v, sW[k * F_OUT + j], acc[j]);
        }
    }

    float di = g_dinv[node];
    float d2 = di * di;
    float* hr = g_H + (long long)node * F_OUT;
    float* ar = bufA(out_sel) + (long long)node * F_OUT;
#pragma unroll
    for (int j = 0; j < F_OUT; j++) {
        hr[j] = acc[j];
        ar[j] = acc[j] * d2;   // self-loop term
    }
}

// ----------------- gather: agg[n] += sum_e w[e] * h[src[e]] ----------------
template <int F>
__global__ void k_gather(int agg_sel, int n)
{
    int node = blockIdx.x * blockDim.y + threadIdx.y;
    if (node >= n) return;
    int f = threadIdx.x;

    float* agg = bufA(agg_sel);
    int e0 = g_off[node];
    int e1 = g_off[node + 1];
    float acc = agg[(long long)node * F + f];   // self-loop already there
    for (int e = e0; e < e1; e++) {
        int   s = g_csrc[e];
        float w = g_cw[e];
        acc = fmaf(g_H[(long long)s * F + f], w, acc);
    }
    agg[(long long)node * F + f] = acc;
}

// ----------------- pool: segment max of relu(agg + b3) ---------------------
__global__ void k_pool(int agg_sel, const float* __restrict__ b3,
                       const int* __restrict__ batch, int n)
{
    int f = threadIdx.x;                              // 0..63
    int chunk = blockIdx.x * blockDim.y + threadIdx.y;
    int n0 = chunk * 16;
    if (n0 >= n) return;
    int n1 = min(n0 + 16, n);
    float bb = b3[f];
    const float* agg = bufA(agg_sel);

    int curg = batch[n0];
    float m = fmaxf(agg[(long long)n0 * 64 + f] + bb, 0.f);
    for (int i = n0 + 1; i < n1; i++) {
        int g = batch[i];
        float v = fmaxf(agg[(long long)i * 64 + f] + bb, 0.f);
        if (g != curg) {
            atomicMax((unsigned int*)&g_pool[curg * 64 + f], __float_as_uint(m));
            curg = g;
            m = v;
        } else {
            m = fmaxf(m, v);
        }
    }
    atomicMax((unsigned int*)&g_pool[curg * 64 + f], __float_as_uint(m));
}

// ----------------------------- MLP head ------------------------------------
__global__ void k_mlp1(const float* __restrict__ W, const float* __restrict__ b)
{
    __shared__ float sp[64];
    int g = blockIdx.x, j = threadIdx.x;   // 256 threads
    if (j < 64) sp[j] = g_pool[g * 64 + j];
    __syncthreads();
    float acc = b[j];
#pragma unroll
    for (int k = 0; k < 64; k++) acc = fmaf(sp[k], W[k * 256 + j], acc);
    g_zbuf[g * 256 + j] = fmaxf(acc, 0.f);
}

__global__ void k_mlp2(const float* __restrict__ W, const float* __restrict__ b,
                       float* __restrict__ out)
{
    __shared__ float sz[256];
    int g = blockIdx.x, j = threadIdx.x;   // 256 threads
    sz[j] = g_zbuf[g * 256 + j];
    __syncthreads();
    float acc = b[j];
#pragma unroll 8
    for (int k = 0; k < 256; k++) acc = fmaf(sz[k], W[k * 256 + j], acc);
    out[g * 256 + j] = 1.f / (1.f + expf(-acc));
}

// ------------------------------ launch -------------------------------------
extern "C" void kernel_launch(void* const* d_in, const int* in_sizes, int n_in,
                              void* d_out, int out_size)
{
    const float* x     = (const float*)d_in[0];
    const int*   ei    = (const int*)d_in[1];    // int32! (JAX x64 disabled)
    const int*   batch = (const int*)d_in[2];
    const float* W1 = (const float*)d_in[3];
    const float* b1 = (const float*)d_in[4];
    const float* W2 = (const float*)d_in[5];
    const float* b2 = (const float*)d_in[6];
    const float* W3 = (const float*)d_in[7];
    const float* b3 = (const float*)d_in[8];
    const float* L1w = (const float*)d_in[9];
    const float* L1b = (const float*)d_in[10];
    const float* L2w = (const float*)d_in[11];
    const float* L2b = (const float*)d_in[12];
    float* out = (float*)d_out;

    int N = in_sizes[0] / 128;
    int E = in_sizes[1] / 2;
    int nblk = (N + SCAN_B - 1) / SCAN_B;

    // CSR build (by destination)
    k_zero    <<<(N + 255) / 256, 256>>>(N);
    k_degcount<<<(E + 255) / 256, 256>>>(ei, E);
    k_dinv    <<<(N + 255) / 256, 256>>>(N);
    k_scan1   <<<nblk, SCAN_B>>>(N);
    k_scan2   <<<1, NBLK_MAX>>>(nblk);
    k_scan3   <<<(N + 255) / 256, 256>>>(N, E);
    k_fill    <<<(E + 255) / 256, 256>>>(ei, E);

    // Layer 1: x[N,128] -> 16 feats
    k_transform<128, 16, false><<<(N + 127) / 128, 128>>>(x, 0, 0, W1, nullptr, N);
    { dim3 b(16, 16); k_gather<16><<<(N + 15) / 16, b>>>(0, N); }

    // Layer 2: relu(A0 + b1) -> 32 feats
    k_transform<16, 32, true><<<(N + 127) / 128, 128>>>(nullptr, 0, 1, W2, b1, N);
    { dim3 b(32, 8);  k_gather<32><<<(N + 7) / 8, b>>>(1, N); }

    // Layer 3: relu(A1 + b2) -> 64 feats
    k_transform<32, 64, true><<<(N + 127) / 128, 128>>>(nullptr, 1, 0, W3, b2, N);
    { dim3 b(64, 4);  k_gather<64><<<(N + 3) / 4, b>>>(0, N); }

    // Pool (batch sorted) + MLP head
    { dim3 pb(64, 4); int chunks = (N + 15) / 16;
      k_pool<<<(chunks + 3) / 4, pb>>>(0, b3, batch, N); }
    k_mlp1<<<G_NUM, 256>>>(L1w, L1b);
    k_mlp2<<<G_NUM, 256>>>(L2w, L2b, out);
}

// round 8
// speedup vs baseline: 1.3085x; 1.3085x over previous
#include <cuda_runtime.h>
#include <math.h>

#define N_MAX 100000
#define E_MAX 1600000
#define G_NUM 1024
#define SCAN_B 1024
#define NBLK_MAX 128   // ceil(100000/1024)=98

// ---------------- device scratch (no allocation allowed) -------------------
__device__ __align__(16) float g_H [(long long)N_MAX * 64]; // pre-scaled feats h' = h*dinv
__device__ __align__(16) float g_A0[(long long)N_MAX * 64]; // agg ping
__device__ __align__(16) float g_A1[(long long)N_MAX * 64]; // agg pong
__device__ float g_dinv[N_MAX];
__device__ int   g_deg [N_MAX];
__device__ int   g_tmp [N_MAX];        // block-scan partials
__device__ int   g_off [N_MAX + 1];    // CSR offsets (by dst)
__device__ int   g_cur [N_MAX];        // fill cursors (seeded to g_off)
__device__ int   g_bsum[NBLK_MAX];     // block sums for scan
__device__ int   g_csrc[E_MAX];        // CSR src ids
__device__ float g_pool[G_NUM * 64];
__device__ float g_zbuf[G_NUM * 256];

__device__ __forceinline__ float* bufA(int s) { return s == 0 ? g_A0 : g_A1; }

// ---------------------------- prep -----------------------------------------
__global__ void k_zero(int n) {
    int i = blockIdx.x * blockDim.x + threadIdx.x;
    if (i < n)          g_deg[i]  = 0;
    if (i < G_NUM * 64) g_pool[i] = 0.f;
}

__global__ void k_degcount(const int* __restrict__ ei, int E) {
    int e = blockIdx.x * blockDim.x + threadIdx.x;
    if (e < E) atomicAdd(&g_deg[ei[E + e]], 1);
}

// ------------------------- 3-kernel exclusive scan --------------------------
__global__ void k_scan1(int n) {
    __shared__ int s[SCAN_B];
    int t = threadIdx.x;
    int i = blockIdx.x * SCAN_B + t;
    int v = (i < n) ? g_deg[i] : 0;
    s[t] = v;
    __syncthreads();
#pragma unroll
    for (int d = 1; d < SCAN_B; d <<= 1) {
        int x = (t >= d) ? s[t - d] : 0;
        __syncthreads();
        s[t] += x;
        __syncthreads();
    }
    if (i < n) g_tmp[i] = s[t];                 // inclusive
    if (t == SCAN_B - 1) g_bsum[blockIdx.x] = s[t];
}

__global__ void k_scan2(int nblk) {
    __shared__ int s[NBLK_MAX];
    int t = threadIdx.x;
    int v = (t < nblk) ? g_bsum[t] : 0;
    s[t] = v;
    __syncthreads();
#pragma unroll
    for (int d = 1; d < NBLK_MAX; d <<= 1) {
        int x = (t >= d) ? s[t - d] : 0;
        __syncthreads();
        s[t] += x;
        __syncthreads();
    }
    if (t < nblk) g_bsum[t] = s[t] - v;         // exclusive
}

__global__ void k_scan3(int n, int E) {
    int i = blockIdx.x * blockDim.x + threadIdx.x;
    if (i < n) {
        int deg = g_deg[i];
        int off = g_tmp[i] - deg + g_bsum[i / SCAN_B];  // exclusive
        g_off[i] = off;
        g_cur[i] = off;                                 // fill cursor = offset
        g_dinv[i] = rsqrtf((float)(deg + 1));           // +1 self loop
    }
    if (i == 0) g_off[n] = E;
}

__global__ void k_fill(const int* __restrict__ ei, int E) {
    int e = blockIdx.x * blockDim.x + threadIdx.x;
    if (e >= E) return;
    int s = ei[e];
    int d = ei[E + e];
    int pos = atomicAdd(&g_cur[d], 1);
    g_csrc[pos] = s;
}

// -------- node transform: h' = (act(in) @ W) * dinv[node]  (pre-scaled) ----
template <int F_IN, int F_OUT, bool RELU_IN>
__global__ void k_transform(const float* __restrict__ x_ext,
                            int in_sel,
                            const float* __restrict__ W,
                            const float* __restrict__ bin, int n)
{
    __shared__ float sW[F_IN * F_OUT];
    __shared__ float sB[F_IN];
    for (int i = threadIdx.x; i < F_IN * F_OUT; i += blockDim.x) sW[i] = W[i];
    if (RELU_IN)
        for (int i = threadIdx.x; i < F_IN; i += blockDim.x) sB[i] = bin[i];
    __syncthreads();

    int node = blockIdx.x * blockDim.x + threadIdx.x;
    if (node >= n) return;

    const float* in = x_ext ? x_ext : bufA(in_sel);
    const float4* row4 = reinterpret_cast<const float4*>(in) +
                         (long long)node * (F_IN / 4);

    float acc[F_OUT];
#pragma unroll
    for (int j = 0; j < F_OUT; j++) acc[j] = 0.f;

    for (int k4 = 0; k4 < F_IN / 4; k4++) {
        float4 v4 = row4[k4];
        float vv[4] = {v4.x, v4.y, v4.z, v4.w};
#pragma unroll
        for (int u = 0; u < 4; u++) {
            int k = k4 * 4 + u;
            float v = vv[u];
            if (RELU_IN) v = fmaxf(v + sB[k], 0.f);
#pragma unroll
            for (int j = 0; j < F_OUT; j++)
                acc[j] = fmaf(v, sW[k * F_OUT + j], acc[j]);
        }
    }

    float di = g_dinv[node];
    float4* hr4 = reinterpret_cast<float4*>(g_H) + (long long)node * (F_OUT / 4);
#pragma unroll
    for (int j4 = 0; j4 < F_OUT / 4; j4++) {
        float4 o;
        o.x = acc[j4 * 4 + 0] * di;
        o.y = acc[j4 * 4 + 1] * di;
        o.z = acc[j4 * 4 + 2] * di;
        o.w = acc[j4 * 4 + 3] * di;
        hr4[j4] = o;
    }
}

// ------ gather: agg[d] = dinv[d] * ( h'[d] + sum_{src->d} h'[src] ) --------
template <int F>
__global__ void k_gather(int agg_sel, int n)
{
    constexpr int L = F / 4;                    // float4 lanes per node
    int node = blockIdx.x * blockDim.y + threadIdx.y;
    if (node >= n) return;
    int f4 = threadIdx.x;                       // 0..L-1

    const float4* H4 = reinterpret_cast<const float4*>(g_H);
    int e0 = g_off[node];
    int e1 = g_off[node + 1];

    float4 a0 = H4[(long long)node * L + f4];   // self-loop term h'[d]
    float4 a1 = make_float4(0.f, 0.f, 0.f, 0.f);

    int e = e0;
    for (; e + 1 < e1; e += 2) {
        int s0 = g_csrc[e];
        int s1 = g_csrc[e + 1];
        float4 v0 = H4[(long long)s0 * L + f4];
        float4 v1 = H4[(long long)s1 * L + f4];
        a0.x += v0.x; a0.y += v0.y; a0.z += v0.z; a0.w += v0.w;
        a1.x += v1.x; a1.y += v1.y; a1.z += v1.z; a1.w += v1.w;
    }
    if (e < e1) {
        int s0 = g_csrc[e];
        float4 v0 = H4[(long long)s0 * L + f4];
        a0.x += v0.x; a0.y += v0.y; a0.z += v0.z; a0.w += v0.w;
    }

    float di = g_dinv[node];
    float4 o;
    o.x = (a0.x + a1.x) * di;
    o.y = (a0.y + a1.y) * di;
    o.z = (a0.z + a1.z) * di;
    o.w = (a0.w + a1.w) * di;
    reinterpret_cast<float4*>(bufA(agg_sel))[(long long)node * L + f4] = o;
}

// ----------------- pool: segment max of relu(agg + b3) ---------------------
__global__ void k_pool(int agg_sel, const float* __restrict__ b3,
                       const int* __restrict__ batch, int n)
{
    int f = threadIdx.x;                              // 0..63
    int chunk = blockIdx.x * blockDim.y + threadIdx.y;
    int n0 = chunk * 16;
    if (n0 >= n) return;
    int n1 = min(n0 + 16, n);
    float bb = b3[f];
    const float* agg = bufA(agg_sel);

    int curg = batch[n0];
    float m = fmaxf(agg[(long long)n0 * 64 + f] + bb, 0.f);
    for (int i = n0 + 1; i < n1; i++) {
        int g = batch[i];
        float v = fmaxf(agg[(long long)i * 64 + f] + bb, 0.f);
        if (g != curg) {
            atomicMax((unsigned int*)&g_pool[curg * 64 + f], __float_as_uint(m));
            curg = g;
            m = v;
        } else {
            m = fmaxf(m, v);
        }
    }
    atomicMax((unsigned int*)&g_pool[curg * 64 + f], __float_as_uint(m));
}

// ----------------------------- MLP head ------------------------------------
__global__ void k_mlp1(const float* __restrict__ W, const float* __restrict__ b)
{
    __shared__ float sp[64];
    int g = blockIdx.x, j = threadIdx.x;   // 256 threads
    if (j < 64) sp[j] = g_pool[g * 64 + j];
    __syncthreads();
    float acc = b[j];
#pragma unroll
    for (int k = 0; k < 64; k++) acc = fmaf(sp[k], W[k * 256 + j], acc);
    g_zbuf[g * 256 + j] = fmaxf(acc, 0.f);
}

__global__ void k_mlp2(const float* __restrict__ W, const float* __restrict__ b,
                       float* __restrict__ out)
{
    __shared__ float sz[256];
    int g = blockIdx.x, j = threadIdx.x;   // 256 threads
    sz[j] = g_zbuf[g * 256 + j];
    __syncthreads();
    float acc = b[j];
#pragma unroll 8
    for (int k = 0; k < 256; k++) acc = fmaf(sz[k], W[k * 256 + j], acc);
    out[g * 256 + j] = 1.f / (1.f + expf(-acc));
}

// ------------------------------ launch -------------------------------------
extern "C" void kernel_launch(void* const* d_in, const int* in_sizes, int n_in,
                              void* d_out, int out_size)
{
    const float* x     = (const float*)d_in[0];
    const int*   ei    = (const int*)d_in[1];    // int32 (JAX x64 disabled)
    const int*   batch = (const int*)d_in[2];
    const float* W1 = (const float*)d_in[3];
    const float* b1 = (const float*)d_in[4];
    const float* W2 = (const float*)d_in[5];
    const float* b2 = (const float*)d_in[6];
    const float* W3 = (const float*)d_in[7];
    const float* b3 = (const float*)d_in[8];
    const float* L1w = (const float*)d_in[9];
    const float* L1b = (const float*)d_in[10];
    const float* L2w = (const float*)d_in[11];
    const float* L2b = (const float*)d_in[12];
    float* out = (float*)d_out;

    int N = in_sizes[0] / 128;
    int E = in_sizes[1] / 2;
    int nblk = (N + SCAN_B - 1) / SCAN_B;

    // CSR build (by destination)
    k_zero    <<<(N + 255) / 256, 256>>>(N);
    k_degcount<<<(E + 255) / 256, 256>>>(ei, E);
    k_scan1   <<<nblk, SCAN_B>>>(N);
    k_scan2   <<<1, NBLK_MAX>>>(nblk);
    k_scan3   <<<(N + 255) / 256, 256>>>(N, E);
    k_fill    <<<(E + 255) / 256, 256>>>(ei, E);

    // Layer 1: x[N,128] -> 16 feats
    k_transform<128, 16, false><<<(N + 127) / 128, 128>>>(x, 0, W1, nullptr, N);
    { dim3 b(4, 64);  k_gather<16><<<(N + 63) / 64, b>>>(0, N); }

    // Layer 2: relu(A0 + b1) -> 32 feats
    k_transform<16, 32, true><<<(N + 127) / 128, 128>>>(nullptr, 0, W2, b1, N);
    { dim3 b(8, 32);  k_gather<32><<<(N + 31) / 32, b>>>(1, N); }

    // Layer 3: relu(A1 + b2) -> 64 feats
    k_transform<32, 64, true><<<(N + 127) / 128, 128>>>(nullptr, 1, W3, b2, N);
    { dim3 b(16, 16); k_gather<64><<<(N + 15) / 16, b>>>(0, N); }

    // Pool (batch sorted) + MLP head
    { dim3 pb(64, 4); int chunks = (N + 15) / 16;
      k_pool<<<(chunks + 3) / 4, pb>>>(0, b3, batch, N); }
    k_mlp1<<<G_NUM, 256>>>(L1w, L1b);
    k_mlp2<<<G_NUM, 256>>>(L2w, L2b, out);
}

// round 9
// speedup vs baseline: 1.3200x; 1.0087x over previous
#include <cuda_runtime.h>
#include <math.h>

#define N_MAX 100000
#define E_MAX 1600000
#define G_NUM 1024
#define SCAN_B 1024
#define NBLK_MAX 128   // ceil(100000/1024)=98

// ---------------- device scratch (no allocation allowed) -------------------
__device__ __align__(16) float g_B0[(long long)N_MAX * 64]; // ping
__device__ __align__(16) float g_B1[(long long)N_MAX * 64]; // pong
__device__ float g_dinv[N_MAX];
__device__ int   g_deg [N_MAX];
__device__ int   g_tmp [N_MAX];        // block-scan partials
__device__ int   g_off [N_MAX + 1];    // CSR offsets (by dst)
__device__ int   g_cur [N_MAX];        // fill cursors (seeded to g_off)
__device__ int   g_bsum[NBLK_MAX];     // block sums for scan
__device__ int   g_csrc[E_MAX];        // CSR src ids
__device__ float g_pool[G_NUM * 64];
__device__ float g_zbuf[G_NUM * 256];

__device__ __forceinline__ float* buf(int s) { return s == 0 ? g_B0 : g_B1; }

// ---------------------------- prep -----------------------------------------
__global__ void k_zero(int n) {
    int i = blockIdx.x * blockDim.x + threadIdx.x;
    if (i < n)          g_deg[i]  = 0;
    if (i < G_NUM * 64) g_pool[i] = 0.f;
}

__global__ void k_degcount(const int* __restrict__ ei, int E) {
    int e = blockIdx.x * blockDim.x + threadIdx.x;
    if (e < E) atomicAdd(&g_deg[ei[E + e]], 1);
}

// ------------------------- 3-kernel exclusive scan --------------------------
__global__ void k_scan1(int n) {
    __shared__ int s[SCAN_B];
    int t = threadIdx.x;
    int i = blockIdx.x * SCAN_B + t;
    int v = (i < n) ? g_deg[i] : 0;
    s[t] = v;
    __syncthreads();
#pragma unroll
    for (int d = 1; d < SCAN_B; d <<= 1) {
        int x = (t >= d) ? s[t - d] : 0;
        __syncthreads();
        s[t] += x;
        __syncthreads();
    }
    if (i < n) g_tmp[i] = s[t];                 // inclusive
    if (t == SCAN_B - 1) g_bsum[blockIdx.x] = s[t];
}

__global__ void k_scan2(int nblk) {
    __shared__ int s[NBLK_MAX];
    int t = threadIdx.x;
    int v = (t < nblk) ? g_bsum[t] : 0;
    s[t] = v;
    __syncthreads();
#pragma unroll
    for (int d = 1; d < NBLK_MAX; d <<= 1) {
        int x = (t >= d) ? s[t - d] : 0;
        __syncthreads();
        s[t] += x;
        __syncthreads();
    }
    if (t < nblk) g_bsum[t] = s[t] - v;         // exclusive
}

__global__ void k_scan3(int n, int E) {
    int i = blockIdx.x * blockDim.x + threadIdx.x;
    if (i < n) {
        int deg = g_deg[i];
        int off = g_tmp[i] - deg + g_bsum[i / SCAN_B];  // exclusive
        g_off[i] = off;
        g_cur[i] = off;
        g_dinv[i] = rsqrtf((float)(deg + 1));           // +1 self loop
    }
    if (i == 0) g_off[n] = E;
}

__global__ void k_fill(const int* __restrict__ ei, int E) {
    int e = blockIdx.x * blockDim.x + threadIdx.x;
    if (e >= E) return;
    int s = ei[e];
    int d = ei[E + e];
    int pos = atomicAdd(&g_cur[d], 1);
    g_csrc[pos] = s;
}

// ---------------------------------------------------------------------------
// Node transform: acc = in @ W, then epilogue:
//   EPI 0: out = acc * dinv                      (pre-scale for next gather)
//   EPI 1: out = relu(acc + b) * dinv            (activation + pre-scale)
//   EPI 2: out = relu(acc + b)                   (final features for pool)
// ---------------------------------------------------------------------------
template <int F_IN, int F_OUT, int EPI>
__global__ void k_transform(const float* __restrict__ x_ext, int in_sel, int out_sel,
                            const float* __restrict__ W,
                            const float* __restrict__ bout, int n)
{
    __shared__ float sW[F_IN * F_OUT];
    for (int i = threadIdx.x; i < F_IN * F_OUT; i += blockDim.x) sW[i] = W[i];
    __syncthreads();

    int node = blockIdx.x * blockDim.x + threadIdx.x;
    if (node >= n) return;

    const float* in = x_ext ? x_ext : buf(in_sel);
    const float4* row4 = reinterpret_cast<const float4*>(in) +
                         (long long)node * (F_IN / 4);

    float acc[F_OUT];
#pragma unroll
    for (int j = 0; j < F_OUT; j++) acc[j] = 0.f;

    for (int k4 = 0; k4 < F_IN / 4; k4++) {
        float4 v4 = row4[k4];
        float vv[4] = {v4.x, v4.y, v4.z, v4.w};
#pragma unroll
        for (int u = 0; u < 4; u++) {
            int k = k4 * 4 + u;
#pragma unroll
            for (int j = 0; j < F_OUT; j++)
                acc[j] = fmaf(vv[u], sW[k * F_OUT + j], acc[j]);
        }
    }

    float di = g_dinv[node];
    float4* out4 = reinterpret_cast<float4*>(buf(out_sel)) +
                   (long long)node * (F_OUT / 4);
#pragma unroll
    for (int j4 = 0; j4 < F_OUT / 4; j4++) {
        float o[4];
#pragma unroll
        for (int u = 0; u < 4; u++) {
            float a = acc[j4 * 4 + u];
            if (EPI == 0)      o[u] = a * di;
            else if (EPI == 1) o[u] = fmaxf(a + bout[j4 * 4 + u], 0.f) * di;
            else               o[u] = fmaxf(a + bout[j4 * 4 + u], 0.f);
        }
        out4[j4] = make_float4(o[0], o[1], o[2], o[3]);
    }
}

// ---------------------------------------------------------------------------
// Warp-per-node gather: m = dinv * ( in[d] + sum_{src->d} in[src] )
//   FUSED=false: out = m
//   FUSED=true : out = relu(m + b) * dinv
// 32 lanes = (32/L) edge slots x L float4-lanes; shfl cross-slot reduction.
// ---------------------------------------------------------------------------
template <int F, bool FUSED>
__global__ void k_gather(int in_sel, int out_sel,
                         const float* __restrict__ bias, int n)
{
    constexpr int L = F / 4;          // float4 lanes per node row
    constexpr int SLOTS = 32 / L;     // parallel edge slots per warp

    int node = blockIdx.x * blockDim.y + threadIdx.y;
    if (node >= n) return;
    int lane = threadIdx.x;
    int slot = lane / L;
    int f4   = lane % L;

    const float4* In4 = reinterpret_cast<const float4*>(buf(in_sel));
    int e0 = g_off[node];
    int e1 = g_off[node + 1];

    float4 a = make_float4(0.f, 0.f, 0.f, 0.f);
    if (slot == 0) a = In4[(long long)node * L + f4];   // self-loop term

    for (int e = e0 + slot; e < e1; e += SLOTS) {
        int s = g_csrc[e];
        float4 v = In4[(long long)s * L + f4];
        a.x += v.x; a.y += v.y; a.z += v.z; a.w += v.w;
    }

#pragma unroll
    for (int off = 16; off >= L; off >>= 1) {
        a.x += __shfl_xor_sync(0xffffffffu, a.x, off);
        a.y += __shfl_xor_sync(0xffffffffu, a.y, off);
        a.z += __shfl_xor_sync(0xffffffffu, a.z, off);
        a.w += __shfl_xor_sync(0xffffffffu, a.w, off);
    }

    if (slot == 0) {
        float di = g_dinv[node];
        float4 o;
        o.x = a.x * di; o.y = a.y * di; o.z = a.z * di; o.w = a.w * di;
        if (FUSED) {
            const float4 b4 = reinterpret_cast<const float4*>(bias)[f4];
            o.x = fmaxf(o.x + b4.x, 0.f) * di;
            o.y = fmaxf(o.y + b4.y, 0.f) * di;
            o.z = fmaxf(o.z + b4.z, 0.f) * di;
            o.w = fmaxf(o.w + b4.w, 0.f) * di;
        }
        reinterpret_cast<float4*>(buf(out_sel))[(long long)node * L + f4] = o;
    }
}

// ----------------- pool: segment max over sorted batch ids -----------------
__global__ void k_pool(int in_sel, const int* __restrict__ batch, int n)
{
    int f = threadIdx.x;                              // 0..63
    int chunk = blockIdx.x * blockDim.y + threadIdx.y;
    int n0 = chunk * 16;
    if (n0 >= n) return;
    int n1 = min(n0 + 16, n);
    const float* h = buf(in_sel);

    int curg = batch[n0];
    float m = h[(long long)n0 * 64 + f];
    for (int i = n0 + 1; i < n1; i++) {
        int g = batch[i];
        float v = h[(long long)i * 64 + f];
        if (g != curg) {
            atomicMax((unsigned int*)&g_pool[curg * 64 + f], __float_as_uint(m));
            curg = g;
            m = v;
        } else {
            m = fmaxf(m, v);
        }
    }
    atomicMax((unsigned int*)&g_pool[curg * 64 + f], __float_as_uint(m));
}

// ----------------------------- MLP head ------------------------------------
__global__ void k_mlp1(const float* __restrict__ W, const float* __restrict__ b)
{
    __shared__ float sp[64];
    int g = blockIdx.x, j = threadIdx.x;   // 256 threads
    if (j < 64) sp[j] = g_pool[g * 64 + j];
    __syncthreads();
    float acc = b[j];
#pragma unroll
    for (int k = 0; k < 64; k++) acc = fmaf(sp[k], W[k * 256 + j], acc);
    g_zbuf[g * 256 + j] = fmaxf(acc, 0.f);
}

__global__ void k_mlp2(const float* __restrict__ W, const float* __restrict__ b,
                       float* __restrict__ out)
{
    __shared__ float sz[256];
    int g = blockIdx.x, j = threadIdx.x;   // 256 threads
    sz[j] = g_zbuf[g * 256 + j];
    __syncthreads();
    float acc = b[j];
#pragma unroll 8
    for (int k = 0; k < 256; k++) acc = fmaf(sz[k], W[k * 256 + j], acc);
    out[g * 256 + j] = 1.f / (1.f + expf(-acc));
}

// ------------------------------ launch -------------------------------------
extern "C" void kernel_launch(void* const* d_in, const int* in_sizes, int n_in,
                              void* d_out, int out_size)
{
    const float* x     = (const float*)d_in[0];
    const int*   ei    = (const int*)d_in[1];    // int32 (JAX x64 disabled)
    const int*   batch = (const int*)d_in[2];
    const float* W1 = (const float*)d_in[3];
    const float* b1 = (const float*)d_in[4];
    const float* W2 = (const float*)d_in[5];
    const float* b2 = (const float*)d_in[6];
    const float* W3 = (const float*)d_in[7];
    const float* b3 = (const float*)d_in[8];
    const float* L1w = (const float*)d_in[9];
    const float* L1b = (const float*)d_in[10];
    const float* L2w = (const float*)d_in[11];
    const float* L2b = (const float*)d_in[12];
    float* out = (float*)d_out;

    int N = in_sizes[0] / 128;
    int E = in_sizes[1] / 2;
    int nblk = (N + SCAN_B - 1) / SCAN_B;

    // CSR build (by destination)
    k_zero    <<<(N + 255) / 256, 256>>>(N);
    k_degcount<<<(E + 255) / 256, 256>>>(ei, E);
    k_scan1   <<<nblk, SCAN_B>>>(N);
    k_scan2   <<<1, NBLK_MAX>>>(nblk);
    k_scan3   <<<(N + 255) / 256, 256>>>(N, E);
    k_fill    <<<(E + 255) / 256, 256>>>(ei, E);

    dim3 gb(32, 8);                       // warp-per-node gathers
    int ggrid = (N + 7) / 8;

    // Layer 1:  q0 = (x @ W1) * dinv                       [N,16] -> buf0
    k_transform<128, 16, 0><<<(N + 127) / 128, 128>>>(x, 0, 0, W1, nullptr, N);
    //           q1 = relu(dinv*(q0+Σq0) + b1) * dinv       [N,16] -> buf1
    k_gather<16, true ><<<ggrid, gb>>>(0, 1, b1, N);

    // Layer 2:  m2 = dinv*(q1+Σq1)                         [N,16] -> buf0
    k_gather<16, false><<<ggrid, gb>>>(1, 0, nullptr, N);
    //           q2 = relu(m2 @ W2 + b2) * dinv             [N,32] -> buf1
    k_transform<16, 32, 1><<<(N + 127) / 128, 128>>>(nullptr, 0, 1, W2, b2, N);

    // Layer 3:  m3 = dinv*(q2+Σq2)                         [N,32] -> buf0
    k_gather<32, false><<<ggrid, gb>>>(1, 0, nullptr, N);
    //           h3 = relu(m3 @ W3 + b3)                    [N,64] -> buf1
    k_transform<32, 64, 2><<<(N + 127) / 128, 128>>>(nullptr, 0, 1, W3, b3, N);

    // Pool (batch sorted) + MLP head
    { dim3 pb(64, 4); int chunks = (N + 15) / 16;
      k_pool<<<(chunks + 3) / 4, pb>>>(1, batch, N); }
    k_mlp1<<<G_NUM, 256>>>(L1w, L1b);
    k_mlp2<<<G_NUM, 256>>>(L2w, L2b, out);
}